// round 12
// baseline (speedup 1.0000x reference)
#include <cuda_runtime.h>

// RoIAlign, NCHW fp32, OUT 7x7, sampling_ratio 2, scale 0.25
// features: (2, 256, 200, 304), rois: (512, 5), out: (512, 256, 7, 7)
//
// Single kernel. Block = (roi, 32-channel group), 8 warps; warp = 4 channels.
// Block prologue precomputes the ROI plan into shared memory:
//   s_x[32]   : per-lane (column, x-weight) — lanes 0..13 corner x0,
//               lanes 16..29 corner x0+1; idle lanes reuse sample 13's
//               column with weight 0 (no extra cache lines).
//   s_plan[14]: per y-sample (rowT*W, rowB*W, wT, wB), 0.25 mean and
//               y-validity folded into the weights
//   s_pack    : 14 x 2-bit transition codes in one int:
//               0 = same rows as prev, 1 = shift down one row, 2 = jump
// Hot loop: FULLY software-pipelined two-row walk. All loads for sample i+1
// (bottom row into pf; on code-2 jumps the top row directly into the dead
// vA registers) issue at the END of iteration i, so no load is consumed in
// the iteration that issues it — unlike rounds 9-11 where code-2 top rows
// were exposed. Consumption is pure register selects. Zero extra registers.
// Epilogue: dual-channel shuffle reduction (round 11) — one shfl_xor(16)
// carries two channels' corner sums, one shfl_xor(1) folds x-pairs, one STG
// writes both channels' bins.

namespace {
constexpr int OUT_H = 7;
constexpr int OUT_W = 7;
constexpr int C     = 256;
constexpr int H     = 200;
constexpr int W     = 304;
constexpr int R     = 512;
constexpr float SCALE = 0.25f;

constexpr int WARPS_PER_BLOCK = 8;
constexpr int GROUPS          = 8;                          // gridDim.y
constexpr int WARPS_PER_ROI   = WARPS_PER_BLOCK * GROUPS;   // 64
constexpr int CH_PER_WARP     = C / WARPS_PER_ROI;          // 4
constexpr int PLANE           = H * W;                      // 60800
constexpr int NSAMP           = OUT_H * 2;                  // 14 y-samples
}

__global__ __launch_bounds__(WARPS_PER_BLOCK * 32)
void roi_align_kernel(const float* __restrict__ feat,
                      const float* __restrict__ rois,
                      float* __restrict__ out)
{
    __shared__ float4 s_plan[NSAMP];  // (offT bits, offB bits, wT, wB)
    __shared__ float2 s_x[32];        // per-lane (col as int bits, wx)
    __shared__ int    s_pack;         // 2-bit codes, sample i at bits [2i,2i+2)
    __shared__ int    s_b;

    const int r    = blockIdx.x;
    const int tid  = threadIdx.x;
    const int lane = tid & 31;

    // ---------- prologue: build the plan ----------
    if (tid < 96) {
        const float rx1 = rois[r * 5 + 1] * SCALE - 0.5f;
        const float ry1 = rois[r * 5 + 2] * SCALE - 0.5f;
        const float rx2 = rois[r * 5 + 3] * SCALE - 0.5f;
        const float ry2 = rois[r * 5 + 4] * SCALE - 0.5f;
        const float bin_w = (rx2 - rx1) * (1.0f / OUT_W);
        const float bin_h = (ry2 - ry1) * (1.0f / OUT_H);

        if (tid == 0) s_b = (int)rois[r * 5 + 0];

        if (tid < NSAMP) {
            const int i = tid;   // y-sample: oy = i>>1, g = i&1
            float yg = ry1 + ((float)(i >> 1) + 0.25f + 0.5f * (float)(i & 1)) * bin_h;
            float vy = ((yg > -1.0f) && (yg < (float)H)) ? 1.0f : 0.0f;
            float yc = fminf(fmaxf(yg, 0.0f), (float)(H - 1));
            int   t  = (int)yc;
            float ly = yc - (float)t;
            int   bb = min(t + 1, H - 1);
            s_plan[i] = make_float4(__int_as_float(t * W), __int_as_float(bb * W),
                                    0.25f * (1.0f - ly) * vy, 0.25f * ly * vy);
        }

        if (tid >= 32 && tid < 64) {
            const int  l   = tid - 32;     // x-table entry
            const int  sx  = l & 15;       // 0..15
            const bool hi  = l >= 16;
            // Idle lanes (sx 14,15) reuse sample 13's column (weight 0).
            const int  sxe = min(sx, 13);
            float x  = rx1 + ((float)(sxe >> 1) + ((float)(sxe & 1) + 0.5f) * 0.5f) * bin_w;
            float vx = ((x > -1.0f) && (x < (float)W) && (sx < 14)) ? 1.0f : 0.0f;
            float xc = fminf(fmaxf(x, 0.0f), (float)(W - 1));
            int   x0 = (int)xc;
            float lx = xc - (float)x0;
            float2 e = hi ? make_float2(__int_as_float(min(x0 + 1, W - 1)), lx * vx)
                          : make_float2(__int_as_float(x0), (1.0f - lx) * vx);
            s_x[l] = e;
        }

        if (tid == 64) {
            // serial recompute of the 14 transition codes into one bitmask
            int pack = 0;
            int prevT = -0x40000000, prevB = -0x40000000;
            #pragma unroll
            for (int i = 0; i < NSAMP; ++i) {
                float yg = ry1 + ((float)(i >> 1) + 0.25f + 0.5f * (float)(i & 1)) * bin_h;
                float yc = fminf(fmaxf(yg, 0.0f), (float)(H - 1));
                int   t  = (int)yc;
                int   bb = min(t + 1, H - 1);
                int code = (t == prevT) ? 0 : ((t == prevB) ? 1 : 2);
                pack |= code << (2 * i);
                prevT = t; prevB = bb;
            }
            s_pack = pack;
        }
    }
    __syncthreads();

    // ---------- hot loop ----------
    const int warpId = tid >> 5;
    const int wroi   = blockIdx.y * WARPS_PER_BLOCK + warpId;  // 0..63
    const int c0     = wroi * CH_PER_WARP;

    const float2 xe   = s_x[lane];
    const int    col  = __float_as_int(xe.x);
    const float  wx   = xe.y;
    const int    pack = s_pack;

    const int  sx     = lane & 15;
    const bool hiHalf = lane >= 16;
    const bool doSt   = (sx < 14) && ((sx & 1) == 0);   // 14 store lanes

    const float* pb = feat + ((size_t)s_b * C + c0) * PLANE + col;
    // per-lane output base: channel parity = half, bin = sx>>1
    float* outB = out + ((size_t)r * C + c0 + (hiHalf ? 1 : 0)) * (OUT_H * OUT_W)
                      + (sx >> 1);

    float vA[CH_PER_WARP], vB[CH_PER_WARP], pf[CH_PER_WARP];
    float bacc[CH_PER_WARP];

    // preload sample 0's rows (code(0) == 2 always): top -> vA, bottom -> pf
    {
        const int2 o0 = *reinterpret_cast<const int2*>(&s_plan[0]);
        #pragma unroll
        for (int cc = 0; cc < CH_PER_WARP; ++cc)
            vA[cc] = __ldg(pb + (size_t)cc * PLANE + o0.x);
        #pragma unroll
        for (int cc = 0; cc < CH_PER_WARP; ++cc)
            pf[cc] = __ldg(pb + (size_t)cc * PLANE + o0.y);
    }

    #pragma unroll
    for (int i = 0; i < NSAMP; ++i) {
        // consumption needs only the weights (offsets live in the prefetch)
        const float2 wts = *reinterpret_cast<const float2*>(
            reinterpret_cast<const char*>(&s_plan[i]) + 8);
        const int code = (pack >> (2 * i)) & 3;

        // resolve rows: pure register selects (code 2's top row is already
        // in vA, prefetched at the end of the previous iteration)
        if (code == 1) {
            #pragma unroll
            for (int cc = 0; cc < CH_PER_WARP; ++cc) vA[cc] = vB[cc];
        }
        if (code != 0) {
            #pragma unroll
            for (int cc = 0; cc < CH_PER_WARP; ++cc) vB[cc] = pf[cc];
        }

        // accumulate this sample into the bin-row accumulator
        if ((i & 1) == 0) {
            #pragma unroll
            for (int cc = 0; cc < CH_PER_WARP; ++cc)
                bacc[cc] = wts.x * vA[cc] + wts.y * vB[cc];
        } else {
            #pragma unroll
            for (int cc = 0; cc < CH_PER_WARP; ++cc)
                bacc[cc] += wts.x * vA[cc] + wts.y * vB[cc];
        }

        // prefetch ALL rows sample i+1 needs (vA is dead past the FMAs above)
        if (i + 1 < NSAMP) {
            const int codeN = (pack >> (2 * (i + 1))) & 3;
            if (codeN != 0) {
                const int2 on = *reinterpret_cast<const int2*>(&s_plan[i + 1]);
                if (codeN == 2) {
                    #pragma unroll
                    for (int cc = 0; cc < CH_PER_WARP; ++cc)
                        vA[cc] = __ldg(pb + (size_t)cc * PLANE + on.x);
                }
                #pragma unroll
                for (int cc = 0; cc < CH_PER_WARP; ++cc)
                    pf[cc] = __ldg(pb + (size_t)cc * PLANE + on.y);
            }
            // codeN == 0: rows unchanged, pf already holds bb(i) == bb(i+1)
        }

        // epilogue on odd samples: dual-channel shuffle reduction
        if ((i & 1) == 1) {
            const int oy = i >> 1;
            #pragma unroll
            for (int pr = 0; pr < CH_PER_WARP / 2; ++pr) {
                float aL = wx * bacc[2 * pr + 0];   // low half's channel
                float aH = wx * bacc[2 * pr + 1];   // high half's channel
                float t  = hiHalf ? aL : aH;
                float rr = __shfl_xor_sync(0xffffffffu, t, 16);
                float s  = (hiHalf ? aH : aL) + rr;        // corner-folded
                s += __shfl_xor_sync(0xffffffffu, s, 1);   // x-pair fold
                if (doSt) {
                    outB[(size_t)(2 * pr) * (OUT_H * OUT_W) + oy * OUT_W] = s;
                }
            }
        }
    }
}

extern "C" void kernel_launch(void* const* d_in, const int* in_sizes, int n_in,
                              void* d_out, int out_size)
{
    const float* feat = (const float*)d_in[0];
    const float* rois = (const float*)d_in[1];
    float*       out  = (float*)d_out;

    dim3 grid(R, GROUPS);
    dim3 block(WARPS_PER_BLOCK * 32);
    roi_align_kernel<<<grid, block>>>(feat, rois, out);
}

// round 13
// speedup vs baseline: 1.0821x; 1.0821x over previous
#include <cuda_runtime.h>

// RoIAlign, NCHW fp32, OUT 7x7, sampling_ratio 2, scale 0.25
// features: (2, 256, 200, 304), rois: (512, 5), out: (512, 256, 7, 7)
//
// Single kernel. Block = (roi, 32-channel group), 8 warps; warp = 4 channels.
// Block prologue precomputes the ROI plan into shared memory:
//   s_x[32]   : per-lane (column, x-weight) — lanes 0..13 corner x0,
//               lanes 16..29 corner x0+1; idle lanes (14,15,30,31) reuse
//               sample 13's column with weight 0 (no extra cache lines).
//   s_plan[14]: per y-sample (rowT*W, rowB*W, wT, wB), 0.25 mean and
//               y-validity folded into the weights
//   s_pack    : 14 x 2-bit transition codes in one int:
//               0 = same rows as prev, 1 = shift down one row, 2 = jump
// Hot loop: software-pipelined two-row register-cache walk (round 9-11).
// Epilogue: dual-channel shuffle reduction — one shfl_xor(16) carries two
// channels' corner sums simultaneously, one shfl_xor(1) folds x-pairs, one
// STG writes both channels' bins.
// NEW: output stores use st.global.cs (evict-first). The 25.7MB write-once
// output stream no longer evicts the ~124.5MB feature set, which almost
// exactly fits the 126MB L2 — protecting feature residency lowers average
// load latency, the dominant cost at 84% occupancy with no saturated pipe.

namespace {
constexpr int OUT_H = 7;
constexpr int OUT_W = 7;
constexpr int C     = 256;
constexpr int H     = 200;
constexpr int W     = 304;
constexpr int R     = 512;
constexpr float SCALE = 0.25f;

constexpr int WARPS_PER_BLOCK = 8;
constexpr int GROUPS          = 8;                          // gridDim.y
constexpr int WARPS_PER_ROI   = WARPS_PER_BLOCK * GROUPS;   // 64
constexpr int CH_PER_WARP     = C / WARPS_PER_ROI;          // 4
constexpr int PLANE           = H * W;                      // 60800
constexpr int NSAMP           = OUT_H * 2;                  // 14 y-samples
}

__global__ __launch_bounds__(WARPS_PER_BLOCK * 32)
void roi_align_kernel(const float* __restrict__ feat,
                      const float* __restrict__ rois,
                      float* __restrict__ out)
{
    __shared__ float2 s_x[32];        // per-lane (col as int bits, wx)
    __shared__ float4 s_plan[NSAMP];  // (offT bits, offB bits, wT, wB)
    __shared__ int    s_pack;         // 2-bit codes, sample i at bits [2i,2i+2)
    __shared__ int    s_b;

    const int r    = blockIdx.x;
    const int tid  = threadIdx.x;
    const int lane = tid & 31;

    // ---------- prologue: build the plan ----------
    if (tid < 96) {
        const float rx1 = rois[r * 5 + 1] * SCALE - 0.5f;
        const float ry1 = rois[r * 5 + 2] * SCALE - 0.5f;
        const float rx2 = rois[r * 5 + 3] * SCALE - 0.5f;
        const float ry2 = rois[r * 5 + 4] * SCALE - 0.5f;
        const float bin_w = (rx2 - rx1) * (1.0f / OUT_W);
        const float bin_h = (ry2 - ry1) * (1.0f / OUT_H);

        if (tid == 0) s_b = (int)rois[r * 5 + 0];

        if (tid < NSAMP) {
            const int i = tid;   // y-sample: oy = i>>1, g = i&1
            float yg = ry1 + ((float)(i >> 1) + 0.25f + 0.5f * (float)(i & 1)) * bin_h;
            float vy = ((yg > -1.0f) && (yg < (float)H)) ? 1.0f : 0.0f;
            float yc = fminf(fmaxf(yg, 0.0f), (float)(H - 1));
            int   t  = (int)yc;
            float ly = yc - (float)t;
            int   bb = min(t + 1, H - 1);
            s_plan[i] = make_float4(__int_as_float(t * W), __int_as_float(bb * W),
                                    0.25f * (1.0f - ly) * vy, 0.25f * ly * vy);
        }

        if (tid >= 32 && tid < 64) {
            const int  l   = tid - 32;     // x-table entry
            const int  sx  = l & 15;       // 0..15
            const bool hi  = l >= 16;
            // Idle lanes (sx 14,15) reuse sample 13's column (weight 0).
            const int  sxe = min(sx, 13);
            float x  = rx1 + ((float)(sxe >> 1) + ((float)(sxe & 1) + 0.5f) * 0.5f) * bin_w;
            float vx = ((x > -1.0f) && (x < (float)W) && (sx < 14)) ? 1.0f : 0.0f;
            float xc = fminf(fmaxf(x, 0.0f), (float)(W - 1));
            int   x0 = (int)xc;
            float lx = xc - (float)x0;
            float2 e = hi ? make_float2(__int_as_float(min(x0 + 1, W - 1)), lx * vx)
                          : make_float2(__int_as_float(x0), (1.0f - lx) * vx);
            s_x[l] = e;
        }

        if (tid == 64) {
            // serial recompute of the 14 transition codes into one bitmask
            int pack = 0;
            int prevT = -0x40000000, prevB = -0x40000000;
            #pragma unroll
            for (int i = 0; i < NSAMP; ++i) {
                float yg = ry1 + ((float)(i >> 1) + 0.25f + 0.5f * (float)(i & 1)) * bin_h;
                float yc = fminf(fmaxf(yg, 0.0f), (float)(H - 1));
                int   t  = (int)yc;
                int   bb = min(t + 1, H - 1);
                int code = (t == prevT) ? 0 : ((t == prevB) ? 1 : 2);
                pack |= code << (2 * i);
                prevT = t; prevB = bb;
            }
            s_pack = pack;
        }
    }
    __syncthreads();

    // ---------- hot loop ----------
    const int warpId = tid >> 5;
    const int wroi   = blockIdx.y * WARPS_PER_BLOCK + warpId;  // 0..63
    const int c0     = wroi * CH_PER_WARP;

    const float2 xe   = s_x[lane];
    const int    col  = __float_as_int(xe.x);
    const float  wx   = xe.y;
    const int    pack = s_pack;

    const int  sx     = lane & 15;
    const bool hiHalf = lane >= 16;
    const bool doSt   = (sx < 14) && ((sx & 1) == 0);   // 14 store lanes

    const float* pb = feat + ((size_t)s_b * C + c0) * PLANE + col;
    // per-lane output base: channel parity = half, bin = sx>>1
    float* outB = out + ((size_t)r * C + c0 + (hiHalf ? 1 : 0)) * (OUT_H * OUT_W)
                      + (sx >> 1);

    float vA[CH_PER_WARP], vB[CH_PER_WARP], pf[CH_PER_WARP];
    float bacc[CH_PER_WARP];

    // preload bottom row of sample 0 (code(0) == 2 always)
    {
        const int offB0 = __float_as_int(s_plan[0].y);
        #pragma unroll
        for (int cc = 0; cc < CH_PER_WARP; ++cc)
            pf[cc] = __ldg(pb + (size_t)cc * PLANE + offB0);
    }

    #pragma unroll
    for (int i = 0; i < NSAMP; ++i) {
        const float4 pe   = s_plan[i];
        const int    code = (pack >> (2 * i)) & 3;

        // resolve top row: select from cache, LDG only on jump
        float nT[CH_PER_WARP];
        if (code == 2) {
            const int offT = __float_as_int(pe.x);
            #pragma unroll
            for (int cc = 0; cc < CH_PER_WARP; ++cc)
                nT[cc] = __ldg(pb + (size_t)cc * PLANE + offT);
        } else {
            #pragma unroll
            for (int cc = 0; cc < CH_PER_WARP; ++cc)
                nT[cc] = (code == 0) ? vA[cc] : vB[cc];
        }
        #pragma unroll
        for (int cc = 0; cc < CH_PER_WARP; ++cc) { vA[cc] = nT[cc]; vB[cc] = pf[cc]; }

        // prefetch bottom row of sample i+1 (independent of this iteration)
        if (i + 1 < NSAMP) {
            const int codeN = (pack >> (2 * (i + 1))) & 3;
            if (codeN != 0) {
                const int offBn = __float_as_int(s_plan[i + 1].y);
                #pragma unroll
                for (int cc = 0; cc < CH_PER_WARP; ++cc)
                    pf[cc] = __ldg(pb + (size_t)cc * PLANE + offBn);
            }
        }

        if ((i & 1) == 0) {
            #pragma unroll
            for (int cc = 0; cc < CH_PER_WARP; ++cc)
                bacc[cc] = pe.z * vA[cc] + pe.w * vB[cc];
        } else {
            #pragma unroll
            for (int cc = 0; cc < CH_PER_WARP; ++cc)
                bacc[cc] += pe.z * vA[cc] + pe.w * vB[cc];

            const int oy = i >> 1;
            // dual-channel reduction: halves carry different channels
            #pragma unroll
            for (int pr = 0; pr < CH_PER_WARP / 2; ++pr) {
                float aL = wx * bacc[2 * pr + 0];   // low half's channel
                float aH = wx * bacc[2 * pr + 1];   // high half's channel
                float t  = hiHalf ? aL : aH;
                float rr = __shfl_xor_sync(0xffffffffu, t, 16);
                float s  = (hiHalf ? aH : aL) + rr;        // corner-folded
                s += __shfl_xor_sync(0xffffffffu, s, 1);   // x-pair fold
                if (doSt) {
                    // evict-first store: keep the write-once output stream
                    // from displacing the L2-resident feature working set
                    __stcs(&outB[(size_t)(2 * pr) * (OUT_H * OUT_W) + oy * OUT_W], s);
                }
            }
        }
    }
}

extern "C" void kernel_launch(void* const* d_in, const int* in_sizes, int n_in,
                              void* d_out, int out_size)
{
    const float* feat = (const float*)d_in[0];
    const float* rois = (const float*)d_in[1];
    float*       out  = (float*)d_out;

    dim3 grid(R, GROUPS);
    dim3 block(WARPS_PER_BLOCK * 32);
    roi_align_kernel<<<grid, block>>>(feat, rois, out);
}

// round 14
// speedup vs baseline: 1.1453x; 1.0584x over previous
#include <cuda_runtime.h>

// RoIAlign, NCHW fp32, OUT 7x7, sampling_ratio 2, scale 0.25
// features: (2, 256, 200, 304), rois: (512, 5), out: (512, 256, 7, 7)
//
// Single kernel. Block = (roi, 32-channel group), 8 warps; warp = 4 channels.
// Block prologue precomputes the ROI plan into shared memory:
//   s_x[32]   : per-lane (column, x-weight) — lanes 0..13 corner x0,
//               lanes 16..29 corner x0+1; idle lanes (14,15,30,31) reuse
//               sample 13's column with weight 0 (no extra cache lines).
//   s_plan[14]: per y-sample (rowT*W, rowB*W, wT, wB), 0.25 mean and
//               y-validity folded into the weights
//   s_pack    : 14 x 2-bit transition codes in one int:
//               0 = same rows as prev, 1 = shift down one row, 2 = jump
// Hot loop: two-row register-cache walk with UNCONDITIONAL bottom-row
// prefetch: pf always loads row bb(i+1) (when codeN==0 this re-reads the
// line already cached in vB — an L1 hit with identical values, so the
// vB<-pf hand-off stays correct). This deletes 13 branch-convergence
// regions from the loop and lets ptxas hoist loads across iterations;
// the only remaining branch is the rare code==2 jump arm.
// Epilogue: dual-channel shuffle reduction — one shfl_xor(16) carries two
// channels' corner sums simultaneously, one shfl_xor(1) folds x-pairs,
// one STG writes both channels' bins.

namespace {
constexpr int OUT_H = 7;
constexpr int OUT_W = 7;
constexpr int C     = 256;
constexpr int H     = 200;
constexpr int W     = 304;
constexpr int R     = 512;
constexpr float SCALE = 0.25f;

constexpr int WARPS_PER_BLOCK = 8;
constexpr int GROUPS          = 8;                          // gridDim.y
constexpr int WARPS_PER_ROI   = WARPS_PER_BLOCK * GROUPS;   // 64
constexpr int CH_PER_WARP     = C / WARPS_PER_ROI;          // 4
constexpr int PLANE           = H * W;                      // 60800
constexpr int NSAMP           = OUT_H * 2;                  // 14 y-samples
}

__global__ __launch_bounds__(WARPS_PER_BLOCK * 32)
void roi_align_kernel(const float* __restrict__ feat,
                      const float* __restrict__ rois,
                      float* __restrict__ out)
{
    __shared__ float2 s_x[32];        // per-lane (col as int bits, wx)
    __shared__ float4 s_plan[NSAMP];  // (offT bits, offB bits, wT, wB)
    __shared__ int    s_pack;         // 2-bit codes, sample i at bits [2i,2i+2)
    __shared__ int    s_b;

    const int r    = blockIdx.x;
    const int tid  = threadIdx.x;
    const int lane = tid & 31;

    // ---------- prologue: build the plan ----------
    if (tid < 96) {
        const float rx1 = rois[r * 5 + 1] * SCALE - 0.5f;
        const float ry1 = rois[r * 5 + 2] * SCALE - 0.5f;
        const float rx2 = rois[r * 5 + 3] * SCALE - 0.5f;
        const float ry2 = rois[r * 5 + 4] * SCALE - 0.5f;
        const float bin_w = (rx2 - rx1) * (1.0f / OUT_W);
        const float bin_h = (ry2 - ry1) * (1.0f / OUT_H);

        if (tid == 0) s_b = (int)rois[r * 5 + 0];

        if (tid < NSAMP) {
            const int i = tid;   // y-sample: oy = i>>1, g = i&1
            float yg = ry1 + ((float)(i >> 1) + 0.25f + 0.5f * (float)(i & 1)) * bin_h;
            float vy = ((yg > -1.0f) && (yg < (float)H)) ? 1.0f : 0.0f;
            float yc = fminf(fmaxf(yg, 0.0f), (float)(H - 1));
            int   t  = (int)yc;
            float ly = yc - (float)t;
            int   bb = min(t + 1, H - 1);
            s_plan[i] = make_float4(__int_as_float(t * W), __int_as_float(bb * W),
                                    0.25f * (1.0f - ly) * vy, 0.25f * ly * vy);
        }

        if (tid >= 32 && tid < 64) {
            const int  l   = tid - 32;     // x-table entry
            const int  sx  = l & 15;       // 0..15
            const bool hi  = l >= 16;
            // Idle lanes (sx 14,15) reuse sample 13's column (weight 0).
            const int  sxe = min(sx, 13);
            float x  = rx1 + ((float)(sxe >> 1) + ((float)(sxe & 1) + 0.5f) * 0.5f) * bin_w;
            float vx = ((x > -1.0f) && (x < (float)W) && (sx < 14)) ? 1.0f : 0.0f;
            float xc = fminf(fmaxf(x, 0.0f), (float)(W - 1));
            int   x0 = (int)xc;
            float lx = xc - (float)x0;
            float2 e = hi ? make_float2(__int_as_float(min(x0 + 1, W - 1)), lx * vx)
                          : make_float2(__int_as_float(x0), (1.0f - lx) * vx);
            s_x[l] = e;
        }

        if (tid == 64) {
            // serial recompute of the 14 transition codes into one bitmask
            int pack = 0;
            int prevT = -0x40000000, prevB = -0x40000000;
            #pragma unroll
            for (int i = 0; i < NSAMP; ++i) {
                float yg = ry1 + ((float)(i >> 1) + 0.25f + 0.5f * (float)(i & 1)) * bin_h;
                float yc = fminf(fmaxf(yg, 0.0f), (float)(H - 1));
                int   t  = (int)yc;
                int   bb = min(t + 1, H - 1);
                int code = (t == prevT) ? 0 : ((t == prevB) ? 1 : 2);
                pack |= code << (2 * i);
                prevT = t; prevB = bb;
            }
            s_pack = pack;
        }
    }
    __syncthreads();

    // ---------- hot loop ----------
    const int warpId = tid >> 5;
    const int wroi   = blockIdx.y * WARPS_PER_BLOCK + warpId;  // 0..63
    const int c0     = wroi * CH_PER_WARP;

    const float2 xe   = s_x[lane];
    const int    col  = __float_as_int(xe.x);
    const float  wx   = xe.y;
    const int    pack = s_pack;

    const int  sx     = lane & 15;
    const bool hiHalf = lane >= 16;
    const bool doSt   = (sx < 14) && ((sx & 1) == 0);   // 14 store lanes

    const float* pb = feat + ((size_t)s_b * C + c0) * PLANE + col;
    // per-lane output base: channel parity = half, bin = sx>>1
    float* outB = out + ((size_t)r * C + c0 + (hiHalf ? 1 : 0)) * (OUT_H * OUT_W)
                      + (sx >> 1);

    float vA[CH_PER_WARP], vB[CH_PER_WARP], pf[CH_PER_WARP];
    float bacc[CH_PER_WARP];

    // preload bottom row of sample 0 (code(0) == 2 always)
    {
        const int offB0 = __float_as_int(s_plan[0].y);
        #pragma unroll
        for (int cc = 0; cc < CH_PER_WARP; ++cc)
            pf[cc] = __ldg(pb + (size_t)cc * PLANE + offB0);
    }

    #pragma unroll
    for (int i = 0; i < NSAMP; ++i) {
        const float4 pe   = s_plan[i];
        const int    code = (pack >> (2 * i)) & 3;

        // resolve top row: select from cache, LDG only on the rare jump
        float nT[CH_PER_WARP];
        if (code == 2) {
            const int offT = __float_as_int(pe.x);
            #pragma unroll
            for (int cc = 0; cc < CH_PER_WARP; ++cc)
                nT[cc] = __ldg(pb + (size_t)cc * PLANE + offT);
        } else {
            #pragma unroll
            for (int cc = 0; cc < CH_PER_WARP; ++cc)
                nT[cc] = (code == 0) ? vA[cc] : vB[cc];
        }
        #pragma unroll
        for (int cc = 0; cc < CH_PER_WARP; ++cc) { vA[cc] = nT[cc]; vB[cc] = pf[cc]; }

        // UNCONDITIONAL prefetch of sample i+1's bottom row: when the rows
        // don't change (code 0) this re-reads the line already in vB — an
        // L1 hit with identical values — in exchange for a branch-free,
        // fully schedulable loop body.
        if (i + 1 < NSAMP) {
            const int offBn = __float_as_int(s_plan[i + 1].y);
            #pragma unroll
            for (int cc = 0; cc < CH_PER_WARP; ++cc)
                pf[cc] = __ldg(pb + (size_t)cc * PLANE + offBn);
        }

        if ((i & 1) == 0) {
            #pragma unroll
            for (int cc = 0; cc < CH_PER_WARP; ++cc)
                bacc[cc] = pe.z * vA[cc] + pe.w * vB[cc];
        } else {
            #pragma unroll
            for (int cc = 0; cc < CH_PER_WARP; ++cc)
                bacc[cc] += pe.z * vA[cc] + pe.w * vB[cc];

            const int oy = i >> 1;
            // dual-channel reduction: halves carry different channels
            #pragma unroll
            for (int pr = 0; pr < CH_PER_WARP / 2; ++pr) {
                float aL = wx * bacc[2 * pr + 0];   // low half's channel
                float aH = wx * bacc[2 * pr + 1];   // high half's channel
                float t  = hiHalf ? aL : aH;
                float rr = __shfl_xor_sync(0xffffffffu, t, 16);
                float s  = (hiHalf ? aH : aL) + rr;        // corner-folded
                s += __shfl_xor_sync(0xffffffffu, s, 1);   // x-pair fold
                if (doSt) {
                    outB[(size_t)(2 * pr) * (OUT_H * OUT_W) + oy * OUT_W] = s;
                }
            }
        }
    }
}

extern "C" void kernel_launch(void* const* d_in, const int* in_sizes, int n_in,
                              void* d_out, int out_size)
{
    const float* feat = (const float*)d_in[0];
    const float* rois = (const float*)d_in[1];
    float*       out  = (float*)d_out;

    dim3 grid(R, GROUPS);
    dim3 block(WARPS_PER_BLOCK * 32);
    roi_align_kernel<<<grid, block>>>(feat, rois, out);
}